// round 1
// baseline (speedup 1.0000x reference)
#include <cuda_runtime.h>
#include <cuda_bf16.h>
#include <cstdint>

// Problem: B=4, S=1024, D=1024, H=16, DH=64
// Pipeline: qp=relu(q@Wq+bq); kp,vp likewise; flash-attn per (b,h); out=relu(ao@Wo+bo)

#define GK 1024
#define GN 1024

// ---------------- scratch ----------------
__device__ float g_qp[4 * 1024 * 1024];
__device__ float g_kp[4 * 1024 * 1024];
__device__ float g_vp[4 * 1024 * 1024];
__device__ float g_ao[4 * 1024 * 1024];

// ---------------- helpers ----------------
__device__ __forceinline__ unsigned f2tf(float x) {
    unsigned r;
    asm("cvt.rna.tf32.f32 %0, %1;" : "=r"(r) : "f"(x));
    return r;
}

__device__ __forceinline__ void mma_tf32(float c[4], const unsigned a[4], const unsigned b[2]) {
    asm volatile(
        "mma.sync.aligned.m16n8k8.row.col.f32.tf32.tf32.f32 "
        "{%0,%1,%2,%3}, {%4,%5,%6,%7}, {%8,%9}, {%0,%1,%2,%3};\n"
        : "+f"(c[0]), "+f"(c[1]), "+f"(c[2]), "+f"(c[3])
        : "r"(a[0]), "r"(a[1]), "r"(a[2]), "r"(a[3]), "r"(b[0]), "r"(b[1]));
}

// ---------------- GEMM: C = relu(A[M,1024] @ W[1024,1024] + bias) ----------------
// BM=128 BN=128 BK=32, 256 threads (8 warps: 4 in M x 2 in N, warp tile 32x64)
constexpr int BM = 128, BN = 128, BK = 32;
constexpr int AST = 36;   // A smem row stride (pad: bank = (4r+c)%32 conflict-free)
constexpr int WST = 132;  // W smem row stride

__global__ void __launch_bounds__(256) gemm_bias_relu(
    const float* __restrict__ A, const float* __restrict__ W,
    const float* __restrict__ bias, float* __restrict__ C, int M)
{
    extern __shared__ float sm[];
    float* As = sm;                 // [2][BM*AST]
    float* Ws = sm + 2 * BM * AST;  // [2][BK*WST]

    const int tid = threadIdx.x;
    const int warp = tid >> 5, lane = tid & 31;
    const int g = lane >> 2, t = lane & 3;
    const int wm = (warp >> 1) * 32;
    const int wn = (warp & 1) * 64;
    const int bm = blockIdx.y * BM;
    const int bn = blockIdx.x * BN;

    float acc[2][8][4];
#pragma unroll
    for (int i = 0; i < 2; i++)
#pragma unroll
        for (int j = 0; j < 8; j++)
#pragma unroll
            for (int k = 0; k < 4; k++) acc[i][j][k] = 0.f;

    auto load_tile = [&](int kt, int buf) {
        const float* Ag = A + (size_t)bm * GK + kt * BK;
#pragma unroll
        for (int i = 0; i < 4; i++) {
            int f = tid + i * 256;
            int r = f >> 3;            // 8 float4 per 32-wide row
            int c = (f & 7) * 4;
            unsigned dst = (unsigned)__cvta_generic_to_shared(&As[buf * BM * AST + r * AST + c]);
            const float* src = Ag + (size_t)r * GK + c;
            asm volatile("cp.async.cg.shared.global [%0], [%1], 16;\n" :: "r"(dst), "l"(src));
        }
        const float* Wg = W + (size_t)(kt * BK) * GN + bn;
#pragma unroll
        for (int i = 0; i < 4; i++) {
            int f = tid + i * 256;
            int r = f >> 5;            // 32 float4 per 128-wide row
            int c = (f & 31) * 4;
            unsigned dst = (unsigned)__cvta_generic_to_shared(&Ws[buf * BK * WST + r * WST + c]);
            const float* src = Wg + (size_t)r * GN + c;
            asm volatile("cp.async.cg.shared.global [%0], [%1], 16;\n" :: "r"(dst), "l"(src));
        }
        asm volatile("cp.async.commit_group;\n" ::: "memory");
    };

    const int NT = GK / BK;  // 32
    load_tile(0, 0);

    for (int kt = 0; kt < NT; kt++) {
        const int buf = kt & 1;
        if (kt + 1 < NT) {
            load_tile(kt + 1, buf ^ 1);
            asm volatile("cp.async.wait_group 1;\n" ::: "memory");
        } else {
            asm volatile("cp.async.wait_group 0;\n" ::: "memory");
        }
        __syncthreads();

        const float* Ab = &As[buf * BM * AST];
        const float* Wb = &Ws[buf * BK * WST];
#pragma unroll
        for (int kk = 0; kk < 4; kk++) {
            unsigned af[2][4];
#pragma unroll
            for (int mf = 0; mf < 2; mf++) {
                int r = wm + mf * 16 + g;
                int c = kk * 8 + t;
                af[mf][0] = f2tf(Ab[r * AST + c]);
                af[mf][1] = f2tf(Ab[(r + 8) * AST + c]);
                af[mf][2] = f2tf(Ab[r * AST + c + 4]);
                af[mf][3] = f2tf(Ab[(r + 8) * AST + c + 4]);
            }
            unsigned bf[8][2];
#pragma unroll
            for (int nf = 0; nf < 8; nf++) {
                int c = wn + nf * 8 + g;
                int r = kk * 8 + t;
                bf[nf][0] = f2tf(Wb[r * WST + c]);
                bf[nf][1] = f2tf(Wb[(r + 4) * WST + c]);
            }
#pragma unroll
            for (int mf = 0; mf < 2; mf++)
#pragma unroll
                for (int nf = 0; nf < 8; nf++)
                    mma_tf32(acc[mf][nf], af[mf], bf[nf]);
        }
        __syncthreads();
    }

    // epilogue: +bias, relu, store
#pragma unroll
    for (int mf = 0; mf < 2; mf++) {
        int r0 = bm + wm + mf * 16 + g;
#pragma unroll
        for (int nf = 0; nf < 8; nf++) {
            int c0 = bn + wn + nf * 8 + t * 2;
            float b0 = bias[c0], b1 = bias[c0 + 1];
            float2 v0 = make_float2(fmaxf(acc[mf][nf][0] + b0, 0.f),
                                    fmaxf(acc[mf][nf][1] + b1, 0.f));
            float2 v1 = make_float2(fmaxf(acc[mf][nf][2] + b0, 0.f),
                                    fmaxf(acc[mf][nf][3] + b1, 0.f));
            *(float2*)&C[(size_t)r0 * GN + c0] = v0;
            *(float2*)&C[(size_t)(r0 + 8) * GN + c0] = v1;
        }
    }
}

// ---------------- Flash attention ----------------
// grid (16, 64): x = q-tile (64 rows), y = b*16+h. 128 threads (4 warps, 16 Q rows each).
constexpr int QST = 68;  // smem row stride for 64-wide tiles

__global__ void __launch_bounds__(128) attn_kernel(
    const float* __restrict__ Q, const float* __restrict__ K,
    const float* __restrict__ V, float* __restrict__ O)
{
    extern __shared__ float sm[];
    float* Qs = sm;              // 64 x QST
    float* Ks = Qs + 64 * QST;
    float* Vs = Ks + 64 * QST;
    float* Ps = Vs + 64 * QST;

    const int tid = threadIdx.x;
    const int warp = tid >> 5, lane = tid & 31;
    const int g = lane >> 2, t = lane & 3;
    const int qt = blockIdx.x;
    const int bh = blockIdx.y;
    const int b = bh >> 4, h = bh & 15;

    const size_t base = (size_t)b * (1024 * 1024) + (size_t)h * 64;  // row stride 1024
    const float* Qg = Q + base + (size_t)qt * 64 * 1024;
    const float* Kg = K + base;
    const float* Vg = V + base;

    // load Q tile, pre-scaled by 1/sqrt(64)
#pragma unroll
    for (int i = 0; i < 8; i++) {
        int f = tid + i * 128;
        int r = f >> 4;
        int c = (f & 15) * 4;
        float4 v = *(const float4*)(Qg + (size_t)r * 1024 + c);
        Qs[r * QST + c + 0] = v.x * 0.125f;
        Qs[r * QST + c + 1] = v.y * 0.125f;
        Qs[r * QST + c + 2] = v.z * 0.125f;
        Qs[r * QST + c + 3] = v.w * 0.125f;
    }

    float oacc[8][4];
#pragma unroll
    for (int nf = 0; nf < 8; nf++)
#pragma unroll
        for (int k = 0; k < 4; k++) oacc[nf][k] = 0.f;
    float mrow[2] = {-1e30f, -1e30f};
    float lrow[2] = {0.f, 0.f};

    const int r0 = warp * 16 + g;

    for (int kt = 0; kt < 16; kt++) {
        __syncthreads();  // protect K/V smem from previous iteration's readers
#pragma unroll
        for (int i = 0; i < 8; i++) {
            int f = tid + i * 128;
            int r = f >> 4;
            int c = (f & 15) * 4;
            *(float4*)&Ks[r * QST + c] = *(const float4*)(Kg + (size_t)(kt * 64 + r) * 1024 + c);
            *(float4*)&Vs[r * QST + c] = *(const float4*)(Vg + (size_t)(kt * 64 + r) * 1024 + c);
        }
        __syncthreads();

        // S = Q @ K^T  (warp computes 16 x 64)
        float sacc[8][4];
#pragma unroll
        for (int nf = 0; nf < 8; nf++)
#pragma unroll
            for (int k = 0; k < 4; k++) sacc[nf][k] = 0.f;

#pragma unroll
        for (int kk = 0; kk < 8; kk++) {
            unsigned af[4];
            af[0] = f2tf(Qs[r0 * QST + kk * 8 + t]);
            af[1] = f2tf(Qs[(r0 + 8) * QST + kk * 8 + t]);
            af[2] = f2tf(Qs[r0 * QST + kk * 8 + t + 4]);
            af[3] = f2tf(Qs[(r0 + 8) * QST + kk * 8 + t + 4]);
#pragma unroll
            for (int nf = 0; nf < 8; nf++) {
                unsigned bf[2];
                bf[0] = f2tf(Ks[(nf * 8 + g) * QST + kk * 8 + t]);
                bf[1] = f2tf(Ks[(nf * 8 + g) * QST + kk * 8 + t + 4]);
                mma_tf32(sacc[nf], af, bf);
            }
        }

        // online softmax (rows g and g+8 of this warp's tile)
#pragma unroll
        for (int rh = 0; rh < 2; rh++) {
            float mx = -1e30f;
#pragma unroll
            for (int nf = 0; nf < 8; nf++)
                mx = fmaxf(mx, fmaxf(sacc[nf][rh * 2], sacc[nf][rh * 2 + 1]));
            mx = fmaxf(mx, __shfl_xor_sync(0xffffffffu, mx, 1));
            mx = fmaxf(mx, __shfl_xor_sync(0xffffffffu, mx, 2));
            float mnew = fmaxf(mrow[rh], mx);
            float alpha = __expf(mrow[rh] - mnew);
            mrow[rh] = mnew;
            float rs = 0.f;
#pragma unroll
            for (int nf = 0; nf < 8; nf++) {
                float p0 = __expf(sacc[nf][rh * 2] - mnew);
                float p1 = __expf(sacc[nf][rh * 2 + 1] - mnew);
                sacc[nf][rh * 2] = p0;
                sacc[nf][rh * 2 + 1] = p1;
                rs += p0 + p1;
            }
            rs += __shfl_xor_sync(0xffffffffu, rs, 1);
            rs += __shfl_xor_sync(0xffffffffu, rs, 2);
            lrow[rh] = lrow[rh] * alpha + rs;
#pragma unroll
            for (int nf = 0; nf < 8; nf++) {
                oacc[nf][rh * 2] *= alpha;
                oacc[nf][rh * 2 + 1] *= alpha;
            }
        }

        // P through warp-private smem to reshape C-frag -> A-frag
#pragma unroll
        for (int nf = 0; nf < 8; nf++) {
            int c = nf * 8 + t * 2;
            *(float2*)&Ps[r0 * QST + c] = make_float2(sacc[nf][0], sacc[nf][1]);
            *(float2*)&Ps[(r0 + 8) * QST + c] = make_float2(sacc[nf][2], sacc[nf][3]);
        }
        __syncwarp();

        // O += P @ V
#pragma unroll
        for (int kk = 0; kk < 8; kk++) {
            unsigned af[4];
            af[0] = f2tf(Ps[r0 * QST + kk * 8 + t]);
            af[1] = f2tf(Ps[(r0 + 8) * QST + kk * 8 + t]);
            af[2] = f2tf(Ps[r0 * QST + kk * 8 + t + 4]);
            af[3] = f2tf(Ps[(r0 + 8) * QST + kk * 8 + t + 4]);
#pragma unroll
            for (int nf = 0; nf < 8; nf++) {
                unsigned bf[2];
                bf[0] = f2tf(Vs[(kk * 8 + t) * QST + nf * 8 + g]);
                bf[1] = f2tf(Vs[(kk * 8 + t + 4) * QST + nf * 8 + g]);
                mma_tf32(oacc[nf], af, bf);
            }
        }
        __syncwarp();
    }

    // normalize and write
    const float inv0 = 1.f / lrow[0];
    const float inv1 = 1.f / lrow[1];
    const int orow = qt * 64 + warp * 16 + g;
    float* Og = O + base;
#pragma unroll
    for (int nf = 0; nf < 8; nf++) {
        int c = nf * 8 + t * 2;
        *(float2*)&Og[(size_t)orow * 1024 + c] =
            make_float2(oacc[nf][0] * inv0, oacc[nf][1] * inv0);
        *(float2*)&Og[(size_t)(orow + 8) * 1024 + c] =
            make_float2(oacc[nf][2] * inv1, oacc[nf][3] * inv1);
    }
}

// ---------------- launch ----------------
extern "C" void kernel_launch(void* const* d_in, const int* in_sizes, int n_in,
                              void* d_out, int out_size)
{
    const float* q  = (const float*)d_in[0];
    const float* k  = (const float*)d_in[1];
    const float* v  = (const float*)d_in[2];
    const float* Wq = (const float*)d_in[3];
    const float* bq = (const float*)d_in[4];
    const float* Wk = (const float*)d_in[5];
    const float* bk = (const float*)d_in[6];
    const float* Wv = (const float*)d_in[7];
    const float* bv = (const float*)d_in[8];
    const float* Wo = (const float*)d_in[9];
    const float* bo = (const float*)d_in[10];
    float* out = (float*)d_out;

    const size_t gemm_smem = (size_t)(2 * BM * AST + 2 * BK * WST) * sizeof(float);  // 70656
    const size_t attn_smem = (size_t)(4 * 64 * QST) * sizeof(float);                 // 69632

    cudaFuncSetAttribute(gemm_bias_relu, cudaFuncAttributeMaxDynamicSharedMemorySize, (int)gemm_smem);
    cudaFuncSetAttribute(attn_kernel,    cudaFuncAttributeMaxDynamicSharedMemorySize, (int)attn_smem);

    float *qp, *kp, *vp, *ao;
    cudaGetSymbolAddress((void**)&qp, g_qp);
    cudaGetSymbolAddress((void**)&kp, g_kp);
    cudaGetSymbolAddress((void**)&vp, g_vp);
    cudaGetSymbolAddress((void**)&ao, g_ao);

    const int M = 4096;  // B*S
    dim3 ggrid(GN / BN, M / BM);  // (8, 32)

    gemm_bias_relu<<<ggrid, 256, gemm_smem>>>(q, Wq, bq, qp, M);
    gemm_bias_relu<<<ggrid, 256, gemm_smem>>>(k, Wk, bk, kp, M);
    gemm_bias_relu<<<ggrid, 256, gemm_smem>>>(v, Wv, bv, vp, M);

    dim3 agrid(16, 64);
    attn_kernel<<<agrid, 128, attn_smem>>>(qp, kp, vp, ao);

    gemm_bias_relu<<<ggrid, 256, gemm_smem>>>(ao, Wo, bo, out, M);
}

// round 14
// speedup vs baseline: 1.1942x; 1.1942x over previous
#include <cuda_runtime.h>
#include <cuda_bf16.h>
#include <cstdint>

// B=4, S=1024, D=1024, H=16, DH=64.  All tensor math via mma.sync tf32 (sm_103 base target).
// Fragment-permuted operand layouts eliminate scalar LDS + per-element cvt.

#define GK 1024
#define GN 1024

// ---------------- scratch ----------------
__device__ float g_qA[4 * 1024 * 1024];
__device__ float g_kA[4 * 1024 * 1024];
__device__ float g_vA[4 * 1024 * 1024];
__device__ float g_wB[4 * 1024 * 1024];
__device__ float g_qp[4 * 1024 * 1024];
__device__ float g_kp[4 * 1024 * 1024];
__device__ float g_vp[4 * 1024 * 1024];
__device__ float g_aoA[4 * 1024 * 1024];

// ---------------- helpers ----------------
__device__ __forceinline__ float rndtf(float x) {
    unsigned r;
    asm("cvt.rna.tf32.f32 %0, %1;" : "=r"(r) : "f"(x));
    return __uint_as_float(r);
}

__device__ __forceinline__ void mma_tf32(float c[4], const unsigned a[4], const unsigned b[2]) {
    asm volatile(
        "mma.sync.aligned.m16n8k8.row.col.f32.tf32.tf32.f32 "
        "{%0,%1,%2,%3}, {%4,%5,%6,%7}, {%8,%9}, {%0,%1,%2,%3};\n"
        : "+f"(c[0]), "+f"(c[1]), "+f"(c[2]), "+f"(c[3])
        : "r"(a[0]), "r"(a[1]), "r"(a[2]), "r"(a[3]), "r"(b[0]), "r"(b[1]));
}

// ---------------- pre-pass: activations -> A-perm (rounded) ----------------
// A-perm global: [MB=M/16][KB=128][lane32][4f];  lane = 4*g + t.
// chunk(lane) = {A[g][t], A[g+8][t], A[g][t+4], A[g+8][t+4]} of block (mb,kb).
__global__ void __launch_bounds__(256) perm_a3(
    const float* __restrict__ q, const float* __restrict__ k, const float* __restrict__ v,
    float4* __restrict__ qA, float4* __restrict__ kA, float4* __restrict__ vA)
{
    int u = blockIdx.x * 256 + threadIdx.x;    // 0 .. 1M-1
    const float* S;
    float4* D;
    if (blockIdx.y == 0)      { S = q; D = qA; }
    else if (blockIdx.y == 1) { S = k; D = kA; }
    else                      { S = v; D = vA; }
    int lane = u & 31, kb = (u >> 5) & 127, mb = u >> 12;
    int g = lane >> 2, t = lane & 3;
    const float* p = S + (size_t)(mb * 16 + g) * GK + kb * 8 + t;
    float4 o;
    o.x = rndtf(p[0]);
    o.y = rndtf(p[8 * GK]);
    o.z = rndtf(p[4]);
    o.w = rndtf(p[8 * GK + 4]);
    D[u] = o;
}

// ---------------- pre-pass: weights -> B-perm (rounded) ----------------
// B-perm global: [NB=128][KB=128][lane32][2f];  lane = 4*g + t.
// chunk(lane) = {W[kb*8+t][nb*8+g], W[kb*8+t+4][nb*8+g]}  (W row-major [K][N]).
__global__ void __launch_bounds__(256) perm_b4(
    const float* __restrict__ w0, const float* __restrict__ w1,
    const float* __restrict__ w2, const float* __restrict__ w3,
    float2* __restrict__ dst)    // 4 segments of 1M floats
{
    int u = blockIdx.x * 256 + threadIdx.x;    // 0 .. 512K-1
    const float* W;
    if (blockIdx.y == 0) W = w0;
    else if (blockIdx.y == 1) W = w1;
    else if (blockIdx.y == 2) W = w2;
    else W = w3;
    float2* D = dst + (size_t)blockIdx.y * (512 * 1024);
    int lane = u & 31, kb = (u >> 5) & 127, nb = u >> 12;
    int g = lane >> 2, t = lane & 3;
    const float* p = W + (size_t)(kb * 8 + t) * GN + nb * 8 + g;
    float2 o;
    o.x = rndtf(p[0]);
    o.y = rndtf(p[4 * GN]);
    D[u] = o;
}

// ---------------- GEMM: C = relu(A @ W + bias), fragment-permuted operands ----------------
// Tile 128x128, BK=32, 3-stage cp.async, 256 threads (8 warps: 4m x 2n, warp 32x64).
constexpr int G_STAGE = 32768;            // A 16KB + B 16KB
constexpr int G_SMEM = 3 * G_STAGE;       // 96KB

__global__ void __launch_bounds__(256, 2) gemm_frag(
    const float4* __restrict__ Ap, const float2* __restrict__ Bp,
    const float* __restrict__ bias, float* __restrict__ C, int roundOut)
{
    extern __shared__ char smc[];
    const int tid = threadIdx.x;
    const int warp = tid >> 5, lane = tid & 31;
    const int g = lane >> 2, t = lane & 3;
    const int wr = warp >> 1, wc = warp & 1;
    const int bmb = blockIdx.y * 8;    // 8 m-blocks per tile
    const int bnb = blockIdx.x * 16;   // 16 n-blocks per tile

    float acc[2][8][4];
#pragma unroll
    for (int i = 0; i < 2; i++)
#pragma unroll
        for (int j = 0; j < 8; j++)
#pragma unroll
            for (int k2 = 0; k2 < 4; k2++) acc[i][j][k2] = 0.f;

    auto load_tile = [&](int kt, int s) {
        char* st = smc + s * G_STAGE;
        // A: 1024 x 16B chunks
#pragma unroll
        for (int i = 0; i < 4; i++) {
            int c = tid + i * 256;
            int ln = c & 31, kb = (c >> 5) & 3, mb = c >> 7;
            const float4* src = Ap + (((size_t)(bmb + mb) * 128 + kt * 4 + kb) * 32 + ln);
            unsigned dst = (unsigned)__cvta_generic_to_shared(st + ((mb * 4 + kb) * 32 + ln) * 16);
            asm volatile("cp.async.cg.shared.global [%0], [%1], 16;\n" :: "r"(dst), "l"(src));
        }
        // B: 1024 x 16B chunks (each covers 2 lanes' float2)
#pragma unroll
        for (int i = 0; i < 4; i++) {
            int c = tid + i * 256;                  // 0..1023
            int lp = c & 15, kb = (c >> 4) & 3, nb = c >> 6;   // nb 0..15
            const float2* src = Bp + (((size_t)(bnb + nb) * 128 + kt * 4 + kb) * 32 + lp * 2);
            unsigned dst = (unsigned)__cvta_generic_to_shared(
                st + 16384 + ((nb * 4 + kb) * 32 + lp * 2) * 8);
            asm volatile("cp.async.cg.shared.global [%0], [%1], 16;\n" :: "r"(dst), "l"(src));
        }
        asm volatile("cp.async.commit_group;\n" ::: "memory");
    };

    const int NT = GK / 32;   // 32
    load_tile(0, 0);
    load_tile(1, 1);

    for (int kt = 0; kt < NT; kt++) {
        if (kt < NT - 1) {
            asm volatile("cp.async.wait_group 1;\n" ::: "memory");
        } else {
            asm volatile("cp.async.wait_group 0;\n" ::: "memory");
        }
        __syncthreads();
        if (kt + 2 < NT) load_tile(kt + 2, (kt + 2) % 3);

        const int s = kt % 3;
        const uint4* Afr = (const uint4*)(smc + s * G_STAGE) + wr * 2 * 4 * 32;   // mb0 = wr*2
        const uint2* Bfr = (const uint2*)(smc + s * G_STAGE + 16384) + wc * 8 * 4 * 32;
#pragma unroll
        for (int kb = 0; kb < 4; kb++) {
            uint4 A0 = Afr[kb * 32 + lane];
            uint4 A1 = Afr[4 * 32 + kb * 32 + lane];
            unsigned a0[4] = {A0.x, A0.y, A0.z, A0.w};
            unsigned a1[4] = {A1.x, A1.y, A1.z, A1.w};
#pragma unroll
            for (int nf = 0; nf < 8; nf++) {
                uint2 Bv = Bfr[(nf * 4 + kb) * 32 + lane];
                unsigned b[2] = {Bv.x, Bv.y};
                mma_tf32(acc[0][nf], a0, b);
                mma_tf32(acc[1][nf], a1, b);
            }
        }
    }

    // epilogue: +bias, relu, optional tf32-round, store row-major
#pragma unroll
    for (int mf = 0; mf < 2; mf++) {
        int r0 = blockIdx.y * 128 + wr * 32 + mf * 16 + g;
#pragma unroll
        for (int nf = 0; nf < 8; nf++) {
            int c0 = blockIdx.x * 128 + wc * 64 + nf * 8 + 2 * t;
            float b0 = bias[c0], b1 = bias[c0 + 1];
            float v0 = fmaxf(acc[mf][nf][0] + b0, 0.f);
            float v1 = fmaxf(acc[mf][nf][1] + b1, 0.f);
            float v2 = fmaxf(acc[mf][nf][2] + b0, 0.f);
            float v3 = fmaxf(acc[mf][nf][3] + b1, 0.f);
            if (roundOut) { v0 = rndtf(v0); v1 = rndtf(v1); v2 = rndtf(v2); v3 = rndtf(v3); }
            *(float2*)&C[(size_t)r0 * GN + c0] = make_float2(v0, v1);
            *(float2*)&C[(size_t)(r0 + 8) * GN + c0] = make_float2(v2, v3);
        }
    }
}

// ---------------- Flash attention, fragment-permuted smem ----------------
// grid (4, 64): x = 256-row q tile, y = b*16+h.  256 threads, 8 warps x 32 rows (mf=2).
// smem: QA 64KB | PA 64KB | KB 16KB | VB 16KB  = 160KB
constexpr int ATT_QA = 0;                 // floats: 16mb x 8kb x 32 x 4
constexpr int ATT_PA = 16384;             // floats
constexpr int ATT_KB = 32768;             // floats: 8nb x 8kb x 32 x 2
constexpr int ATT_VB = 36864;             // floats
constexpr int ATT_SMEM = 40960 * 4;       // bytes

__global__ void __launch_bounds__(256, 1) attn2(
    const float* __restrict__ qp, const float* __restrict__ kp,
    const float* __restrict__ vp, float* __restrict__ aoA)
{
    extern __shared__ float sm[];
    float* QA = sm + ATT_QA;
    float* PA = sm + ATT_PA;
    float* KB = sm + ATT_KB;
    float* VB = sm + ATT_VB;

    const int tid = threadIdx.x;
    const int warp = tid >> 5, lane = tid & 31;
    const int g = lane >> 2, t = lane & 3;
    const int qt = blockIdx.x;
    const int bh = blockIdx.y;
    const int b = bh >> 4, h = bh & 15;

    const float* Qg = qp + ((size_t)b * 1024 + qt * 256) * GK + h * 64;
    const float* Kg = kp + (size_t)b * 1024 * GK + h * 64;
    const float* Vg = vp + (size_t)b * 1024 * GK + h * 64;

    // Q fill: gather into A-perm, scaled by 1/sqrt(64) (exact power of 2)
#pragma unroll
    for (int i = 0; i < 16; i++) {
        int u = tid + i * 256;                   // 0..4095
        int ln = u & 31, kb = (u >> 5) & 7, mb = u >> 8;
        int gg = ln >> 2, tt = ln & 3;
        const float* p = Qg + (size_t)(mb * 16 + gg) * GK + kb * 8 + tt;
        float4 o;
        o.x = p[0] * 0.125f;
        o.y = p[8 * GK] * 0.125f;
        o.z = p[4] * 0.125f;
        o.w = p[8 * GK + 4] * 0.125f;
        *(float4*)&QA[u * 4] = o;
    }

    float oacc[2][8][4];
#pragma unroll
    for (int mf = 0; mf < 2; mf++)
#pragma unroll
        for (int nf = 0; nf < 8; nf++)
#pragma unroll
            for (int k2 = 0; k2 < 4; k2++) oacc[mf][nf][k2] = 0.f;
    float mrow[2][2] = {{-1e30f, -1e30f}, {-1e30f, -1e30f}};
    float lrow[2][2] = {{0.f, 0.f}, {0.f, 0.f}};

    for (int kt = 0; kt < 16; kt++) {
        __syncthreads();   // prior PV reads of KB/VB complete
        // K fill: B-perm {K[nb*8+g][kb*8+t], [t+4]}
        const float* Kt = Kg + (size_t)kt * 64 * GK;
#pragma unroll
        for (int i = 0; i < 8; i++) {
            int u = tid + i * 256;               // 0..2047
            int ln = u & 31, kb = (u >> 5) & 7, nb = u >> 8;
            int gg = ln >> 2, tt = ln & 3;
            const float* p = Kt + (size_t)(nb * 8 + gg) * GK + kb * 8 + tt;
            *(float2*)&KB[u * 2] = make_float2(p[0], p[4]);
        }
        // V fill: B-perm {V[kb*8+t][nb*8+g], V[kb*8+t+4][nb*8+g]}
        const float* Vt = Vg + (size_t)kt * 64 * GK;
#pragma unroll
        for (int i = 0; i < 8; i++) {
            int u = tid + i * 256;
            int ln = u & 31, kb = (u >> 5) & 7, nb = u >> 8;
            int gg = ln >> 2, tt = ln & 3;
            const float* p = Vt + (size_t)(kb * 8 + tt) * GK + nb * 8 + gg;
            *(float2*)&VB[u * 2] = make_float2(p[0], p[4 * GK]);
        }
        __syncthreads();

        // S = Q @ K^T (warp: 32 x 64)
        float sacc[2][8][4];
#pragma unroll
        for (int mf = 0; mf < 2; mf++)
#pragma unroll
            for (int nf = 0; nf < 8; nf++)
#pragma unroll
                for (int k2 = 0; k2 < 4; k2++) sacc[mf][nf][k2] = 0.f;

#pragma unroll
        for (int kb = 0; kb < 8; kb++) {
            uint4 A0 = *(const uint4*)&QA[(((warp * 2 + 0) * 8 + kb) * 32 + lane) * 4];
            uint4 A1 = *(const uint4*)&QA[(((warp * 2 + 1) * 8 + kb) * 32 + lane) * 4];
            unsigned a0[4] = {A0.x, A0.y, A0.z, A0.w};
            unsigned a1[4] = {A1.x, A1.y, A1.z, A1.w};
#pragma unroll
            for (int nf = 0; nf < 8; nf++) {
                uint2 Bv = *(const uint2*)&KB[((nf * 8 + kb) * 32 + lane) * 2];
                unsigned bb[2] = {Bv.x, Bv.y};
                mma_tf32(sacc[0][nf], a0, bb);
                mma_tf32(sacc[1][nf], a1, bb);
            }
        }

        // online softmax per (mf, row-half)
#pragma unroll
        for (int mf = 0; mf < 2; mf++) {
#pragma unroll
            for (int rh = 0; rh < 2; rh++) {
                const int i0 = rh * 2;
                float mx = -1e30f;
#pragma unroll
                for (int nf = 0; nf < 8; nf++)
                    mx = fmaxf(mx, fmaxf(sacc[mf][nf][i0], sacc[mf][nf][i0 + 1]));
                mx = fmaxf(mx, __shfl_xor_sync(0xffffffffu, mx, 1));
                mx = fmaxf(mx, __shfl_xor_sync(0xffffffffu, mx, 2));
                float mnew = fmaxf(mrow[mf][rh], mx);
                float alpha = __expf(mrow[mf][rh] - mnew);
                mrow[mf][rh] = mnew;
                float rs = 0.f;
#pragma unroll
                for (int nf = 0; nf < 8; nf++) {
                    float p0 = __expf(sacc[mf][nf][i0] - mnew);
                    float p1 = __expf(sacc[mf][nf][i0 + 1] - mnew);
                    sacc[mf][nf][i0] = p0;
                    sacc[mf][nf][i0 + 1] = p1;
                    rs += p0 + p1;
                }
                rs += __shfl_xor_sync(0xffffffffu, rs, 1);
                rs += __shfl_xor_sync(0xffffffffu, rs, 2);
                lrow[mf][rh] = lrow[mf][rh] * alpha + rs;
#pragma unroll
                for (int nf = 0; nf < 8; nf++) {
                    oacc[mf][nf][i0] *= alpha;
                    oacc[mf][nf][i0 + 1] *= alpha;
                }
            }
        }

        // P -> PA in A-perm layout (rounded).  C-frag (g,t): cols 2t,2t+1; rows g,g+8.
#pragma unroll
        for (int mf = 0; mf < 2; mf++) {
#pragma unroll
            for (int nf = 0; nf < 8; nf++) {
                int base = ((((warp * 2 + mf) * 8 + nf) * 32) + 4 * g + 2 * (t & 1)) * 4
                           + (t >> 1) * 2;
                *(float2*)&PA[base] =
                    make_float2(rndtf(sacc[mf][nf][0]), rndtf(sacc[mf][nf][2]));
                *(float2*)&PA[base + 4] =
                    make_float2(rndtf(sacc[mf][nf][1]), rndtf(sacc[mf][nf][3]));
            }
        }
        __syncwarp();

        // O += P @ V
#pragma unroll
        for (int kb = 0; kb < 8; kb++) {
            uint4 A0 = *(const uint4*)&PA[(((warp * 2 + 0) * 8 + kb) * 32 + lane) * 4];
            uint4 A1 = *(const uint4*)&PA[(((warp * 2 + 1) * 8 + kb) * 32 + lane) * 4];
            unsigned a0[4] = {A0.x, A0.y, A0.z, A0.w};
            unsigned a1[4] = {A1.x, A1.y, A1.z, A1.w};
#pragma unroll
            for (int nf = 0; nf < 8; nf++) {
                uint2 Bv = *(const uint2*)&VB[((nf * 8 + kb) * 32 + lane) * 2];
                unsigned bb[2] = {Bv.x, Bv.y};
                mma_tf32(oacc[0][nf], a0, bb);
                mma_tf32(oacc[1][nf], a1, bb);
            }
        }
        __syncwarp();
    }

    // normalize + round + write directly into global A-perm layout for the final GEMM
#pragma unroll
    for (int mf = 0; mf < 2; mf++) {
        float inv0 = 1.f / lrow[mf][0];
        float inv1 = 1.f / lrow[mf][1];
        int mb_g = (bh >> 4) * 64 + qt * 16 + warp * 2 + mf;
#pragma unroll
        for (int nf = 0; nf < 8; nf++) {
            int kb_g = (bh & 15) * 8 + nf;
            float* dst = aoA + (((size_t)mb_g * 128 + kb_g) * 32) * 4;
            int off = (4 * g + 2 * (t & 1)) * 4 + (t >> 1) * 2;
            *(float2*)&dst[off] = make_float2(rndtf(oacc[mf][nf][0] * inv0),
                                              rndtf(oacc[mf][nf][2] * inv1));
            *(float2*)&dst[off + 4] = make_float2(rndtf(oacc[mf][nf][1] * inv0),
                                                  rndtf(oacc[mf][nf][3] * inv1));
        }
    }
}

// ---------------- launch ----------------
extern "C" void kernel_launch(void* const* d_in, const int* in_sizes, int n_in,
                              void* d_out, int out_size)
{
    const float* q  = (const float*)d_in[0];
    const float* k  = (const float*)d_in[1];
    const float* v  = (const float*)d_in[2];
    const float* Wq = (const float*)d_in[3];
    const float* bq = (const float*)d_in[4];
    const float* Wk = (const float*)d_in[5];
    const float* bk = (const float*)d_in[6];
    const float* Wv = (const float*)d_in[7];
    const float* bv = (const float*)d_in[8];
    const float* Wo = (const float*)d_in[9];
    const float* bo = (const float*)d_in[10];
    float* out = (float*)d_out;

    float *qA, *kA, *vA, *wB, *qp, *kp, *vp, *aoA;
    cudaGetSymbolAddress((void**)&qA, g_qA);
    cudaGetSymbolAddress((void**)&kA, g_kA);
    cudaGetSymbolAddress((void**)&vA, g_vA);
    cudaGetSymbolAddress((void**)&wB, g_wB);
    cudaGetSymbolAddress((void**)&qp, g_qp);
    cudaGetSymbolAddress((void**)&kp, g_kp);
    cudaGetSymbolAddress((void**)&vp, g_vp);
    cudaGetSymbolAddress((void**)&aoA, g_aoA);

    cudaFuncSetAttribute(gemm_frag, cudaFuncAttributeMaxDynamicSharedMemorySize, G_SMEM);
    cudaFuncSetAttribute(attn2, cudaFuncAttributeMaxDynamicSharedMemorySize, ATT_SMEM);

    // pre-passes
    dim3 pa_grid(4096, 3);
    perm_a3<<<pa_grid, 256>>>(q, k, v, (float4*)qA, (float4*)kA, (float4*)vA);
    dim3 pb_grid(2048, 4);
    perm_b4<<<pb_grid, 256>>>(Wq, Wk, Wv, Wo, (float2*)wB);

    // projections (rounded outputs feed attention mma directly)
    dim3 ggrid(8, 32);
    gemm_frag<<<ggrid, 256, G_SMEM>>>((const float4*)qA, (const float2*)(wB + 0 * 1024 * 1024),
                                      bq, qp, 1);
    gemm_frag<<<ggrid, 256, G_SMEM>>>((const float4*)kA, (const float2*)(wB + 1 * 1024 * 1024),
                                      bk, kp, 1);
    gemm_frag<<<ggrid, 256, G_SMEM>>>((const float4*)vA, (const float2*)(wB + 2 * 1024 * 1024),
                                      bv, vp, 1);

    // attention (writes aoA in global A-perm layout)
    dim3 agrid(4, 64);
    attn2<<<agrid, 256, ATT_SMEM>>>(qp, kp, vp, aoA);

    // output projection (no rounding of final result)
    gemm_frag<<<ggrid, 256, G_SMEM>>>((const float4*)aoA, (const float2*)(wB + 3 * 1024 * 1024),
                                      bo, out, 0);
}